// round 13
// baseline (speedup 1.0000x reference)
#include <cuda_runtime.h>
#include <math.h>

// ---------------------------------------------------------------------------
// QNetBlock: 18-qubit state-vector sim, batch 32.
//   out = | P2 * D2 * P1 * D1 * x | / ||x||
// Per layer D = Phi_out * (tensor RY) * Phi_in (Phi diagonal, RY real).
// R11: RY butterflies in TANGENT form: [c,-s;s,c] = c*[1,-t;t,1], t=tan(th/2).
//   scaled butterfly = 2 wide FMA per pair (1 per amp); the deferred scale
//   prod(cos) folds free into the load diagonals / invnorm. [1,-t;t,1] is a
//   scaled rotation (condition number 1) -> no error amplification.
// Bit split: low = bits 0..11, high = 12..17.  4-pass schedule:
//   pass1: Phi_in,lo(L0) + RY bits 0..11.
//   pass2: [Phi_in,hi(L0)*Phi_out,lo(L0)] + RY 12..17 + Phi_out,hi(L0) + P1.
//   pass3: Phi_in,lo(L1) + RY bits 0..11 (in-place).
//   pass4: Phi_in,hi(L1) + RY 12..17; Phi_out(L1) dropped; P2 + |amp|/||x||.
// 16 amps/thread, 256-thread CTAs, launch_bounds(256,3)  (R6 config, best).
// ---------------------------------------------------------------------------

#define NB      32
#define NSTATE  (1 << 18)
#define CHUNK   4096
#define NCHK    64

typedef unsigned long long u64;

__device__ u64   g_sa[(size_t)NB * NSTATE];   // 64 MB
__device__ u64   g_sb[(size_t)NB * NSTATE];   // 64 MB
__device__ float g_partial[NB * NCHK];
__device__ float g_invnorm[NB];

struct PermM { unsigned m[18]; };

// ---- packed f32x2 helpers --------------------------------------------------
__device__ __forceinline__ u64 pk(float x, float y) {
    u64 r; asm("mov.b64 %0,{%1,%2};" : "=l"(r) : "f"(x), "f"(y)); return r;
}
__device__ __forceinline__ void up(u64 a, float& x, float& y) {
    asm("mov.b64 {%0,%1},%2;" : "=f"(x), "=f"(y) : "l"(a));
}
__device__ __forceinline__ u64 f2mul(u64 a, u64 b) {
    u64 r; asm("mul.rn.f32x2 %0,%1,%2;" : "=l"(r) : "l"(a), "l"(b)); return r;
}
__device__ __forceinline__ u64 f2fma(u64 a, u64 b, u64 c) {
    u64 r; asm("fma.rn.f32x2 %0,%1,%2,%3;" : "=l"(r) : "l"(a), "l"(b), "l"(c)); return r;
}
__device__ __forceinline__ u64 cmulp(u64 a, u64 b) {
    float ax, ay, bx, by; up(a, ax, ay); up(b, bx, by);
    return pk(fmaf(ax, bx, -ay * by), fmaf(ax, by, ay * bx));
}
// tangent-form scaled RY butterfly: A' = A - t*B ; B' = B + t*A   (2 wide FMA)
__device__ __forceinline__ void bflyT(u64& A, u64& B, u64 t2, u64 nt2) {
    u64 nA = f2fma(nt2, B, A);
    B      = f2fma(t2,  A, B);
    A      = nA;
}

// swizzle: conflict-free/2-phase-min for all ownership patterns used below
__device__ __forceinline__ int sw16(int i) { return i ^ ((i >> 4) & 15); }

// ---------------------------------------------------------------------------
// pass_low: one layer's RY gates on bits 0..11 + Phi_in,lo (incl. tan-scale
// compensation prod(cos)) at load. CTA = contiguous 4096-amp chunk;
// 256 threads x 16 packed amps. Ownerships A: bits 8..11 ; B: 0..3 ; C: 4..7.
// ---------------------------------------------------------------------------
template<bool FIRST>
__global__ void __launch_bounds__(256, 3)
pass_low(const float* __restrict__ x, const float* __restrict__ params,
         u64* __restrict__ dst, const u64* __restrict__ src)
{
    extern __shared__ u64 smem[];          // 4096 u64 = 32 KB
    __shared__ float sp[54];
    __shared__ u64   T2[12], NT2[12], Tin[16];
    __shared__ float csh[12];
    __shared__ float wsum[8];

    int t  = threadIdx.x;
    int b  = blockIdx.x >> 6;
    int ch = blockIdx.x & 63;
    int base = b * NSTATE + ch * CHUNK;

    u64 v[16];
    float xr[16];
    if (FIRST) {
        float ss = 0.f;
#pragma unroll
        for (int k = 0; k < 16; k++) {
            float xv = x[base + t + 256 * k];
            xr[k] = xv;
            ss += xv * xv;
        }
#pragma unroll
        for (int o = 16; o; o >>= 1) ss += __shfl_down_sync(0xffffffffu, ss, o);
        if ((t & 31) == 0) wsum[t >> 5] = ss;
    } else {
#pragma unroll
        for (int k = 0; k < 16; k++) v[k] = src[base + t + 256 * k];
    }
    if (t < 54) sp[t] = params[t];
    __syncthreads();                       // sp + wsum ready

    if (FIRST && t == 0) {
        float s = 0.f;
        for (int i = 0; i < 8; i++) s += wsum[i];
        g_partial[blockIdx.x] = s;         // deterministic fixed-order sum
    }

    if (t < 12) {                          // tan tables for bit p = t (wire 17-t)
        float s, c; sincosf(0.5f * sp[(17 - t) * 3 + 1], &s, &c);
        float tn = s / c;
        T2[t] = pk(tn, tn); NT2[t] = pk(-tn, -tn); csh[t] = c;
    } else if (t >= 32 && t < 48) {        // Phi_in table over bits 8..11
        int k = t - 32; float a = 0.f;
#pragma unroll
        for (int j = 0; j < 4; j++)
            if ((k >> j) & 1) a += sp[(17 - (8 + j)) * 3 + 0];
        float s, c; sincosf(a, &s, &c); Tin[k] = pk(c, s);
    }
    // per-thread Phi_in base: bits 0..7 of t, plus global -sum/2 over bits 0..11
    float ang = 0.f;
#pragma unroll
    for (int p = 0; p < 12; p++) {
        float ph = sp[(17 - p) * 3 + 0];
        ang -= 0.5f * ph;
        if (p < 8 && ((t >> p) & 1)) ang += ph;
    }
    float fs, fc; sincosf(ang, &fs, &fc);
    __syncthreads();                       // tables ready

    // tan-scale compensation: C = prod cos(theta_p/2), p = 0..11
    float C = ((csh[0] * csh[1]) * (csh[2] * csh[3]))
            * ((csh[4] * csh[5]) * (csh[6] * csh[7]))
            * ((csh[8] * csh[9]) * (csh[10] * csh[11]));
    u64 pf0 = pk(C * fc, C * fs);

    // Phi_in,lo (scaled)  (FIRST: real input -> one packed mul per amp)
#pragma unroll
    for (int k = 0; k < 16; k++) {
        u64 fk = cmulp(pf0, Tin[k]);
        if (FIRST) v[k] = f2mul(pk(xr[k], xr[k]), fk);
        else       v[k] = cmulp(v[k], fk);
    }

    // Ownership A: RY bits 8..11
#pragma unroll
    for (int kb = 0; kb < 4; kb++) {
        int m = 1 << kb;
        u64 t2 = T2[8 + kb], n2 = NT2[8 + kb];
#pragma unroll
        for (int k = 0; k < 16; k++)
            if (!(k & m)) bflyT(v[k], v[k + m], t2, n2);
    }
#pragma unroll
    for (int k = 0; k < 16; k++) smem[sw16(t + 256 * k)] = v[k];
    __syncthreads();

    // Ownership B: elem = t*16 + k -> RY bits 0..3
#pragma unroll
    for (int k = 0; k < 16; k++) v[k] = smem[sw16(t * 16 + k)];
#pragma unroll
    for (int kb = 0; kb < 4; kb++) {
        int m = 1 << kb;
        u64 t2 = T2[kb], n2 = NT2[kb];
#pragma unroll
        for (int k = 0; k < 16; k++)
            if (!(k & m)) bflyT(v[k], v[k + m], t2, n2);
    }
#pragma unroll
    for (int k = 0; k < 16; k++) smem[sw16(t * 16 + k)] = v[k];
    __syncthreads();

    // Ownership C: elem = r + 16k + 256h -> RY bits 4..7, coalesced store
    int r = t & 15, h = t >> 4;
#pragma unroll
    for (int k = 0; k < 16; k++) v[k] = smem[sw16(r + 16 * k + 256 * h)];
#pragma unroll
    for (int kb = 0; kb < 4; kb++) {
        int m = 1 << kb;
        u64 t2 = T2[4 + kb], n2 = NT2[4 + kb];
#pragma unroll
        for (int k = 0; k < 16; k++)
            if (!(k & m)) bflyT(v[k], v[k + m], t2, n2);
    }
#pragma unroll
    for (int k = 0; k < 16; k++)
        dst[base + r + 16 * k + 256 * h] = v[k];
}

// ---------------------------------------------------------------------------
// pass_high: one layer's RY gates on bits 12..17 (tan form) in two stages
// through one smem transpose, diagonals at load/store (tan-scale prod(cos)
// folded into pg for !LAST and into invnorm for LAST), CNOT-ring permutation
// as XOR-mask scatter at store.
// ---------------------------------------------------------------------------
template<bool LAST>
__global__ void __launch_bounds__(256, 3)
pass_high(const float* __restrict__ params, PermM P,
          const u64* __restrict__ src, u64* __restrict__ dst,
          float* __restrict__ outF)
{
    extern __shared__ u64 stage[];               // 4096 u64 = 32 KB
    __shared__ float sp[54];
    __shared__ u64   T2[6], NT2[6], Hin[64], Hout[64];
    __shared__ float csh[6];

    int t    = threadIdx.x;
    int hi2  = t >> 6;                           // source bits 16..17 (stage A)
    int b    = blockIdx.x >> 6;
    int fix  = blockIdx.x & 63;                  // source bits 6..11
    int off_lo = (t & 63) | (fix << 6);          // source bits 0..11
    int base = b * NSTATE + off_lo + (hi2 << 16);

    u64 v[16];
#pragma unroll
    for (int k = 0; k < 16; k++) v[k] = src[base + (k << 12)];  // coalesced

    if (t < 54) sp[t] = params[t];
    __syncthreads();

    if (t < 6) {                                 // tan for bit 12+t = wire 5-t
        float s, c; sincosf(0.5f * sp[(5 - t) * 3 + 1], &s, &c);
        float tn = s / c;
        T2[t] = pk(tn, tn); NT2[t] = pk(-tn, -tn); csh[t] = c;
    } else if (t >= 64 && t < 128) {             // tables over bits 12..17
        int kk = t - 64;
        float ai = 0.f, ao = 0.f;
#pragma unroll
        for (int j = 0; j < 6; j++) {
            float ph = sp[(5 - j) * 3 + 0];
            float om = sp[(5 - j) * 3 + 2];
            ai -= 0.5f * ph;  ao -= 0.5f * om;
            if ((kk >> j) & 1) { ai += ph; ao += om; }
        }
        float s, c;
        sincosf(ai, &s, &c); Hin[kk] = pk(c, s);
        if (!LAST) { sincosf(ao, &s, &c); Hout[kk] = pk(c, s); }
    }
    // per-thread Phi_out,lo(L0) phasor (only !LAST); built after sync w/ C6
    float s0 = 0.f, c0 = 1.f;
    if (!LAST) {
        float ang = 0.f;
#pragma unroll
        for (int p = 0; p < 12; p++) {
            float om = sp[(17 - p) * 3 + 2];
            ang -= 0.5f * om;
            if ((off_lo >> p) & 1) ang += om;
        }
        sincosf(ang, &s0, &c0);
    }
    __syncthreads();

    // tan-scale compensation for the 6 high levels
    float C6 = (csh[0] * csh[1]) * (csh[2] * csh[3]) * (csh[4] * csh[5]);
    u64 pg = pk(C6 * c0, C6 * s0);               // !LAST: scaled Phi_out,lo(L0)

    // load diagonal: source bits 12..17 = k | hi2<<4
#pragma unroll
    for (int k = 0; k < 16; k++) {
        u64 f = Hin[k | (hi2 << 4)];
        if (!LAST) f = cmulp(pg, f);
        v[k] = cmulp(v[k], f);
    }

    // Stage A: RY bits 12..15 (k bits 0..3)
#pragma unroll
    for (int kb = 0; kb < 4; kb++) {
        int m = 1 << kb;
        u64 t2 = T2[kb], n2 = NT2[kb];
#pragma unroll
        for (int k = 0; k < 16; k++)
            if (!(k & m)) bflyT(v[k], v[k + m], t2, n2);
    }

    // transpose: local L = srcbits{0..5} | {12..15}<<6 | {16..17}<<10
#pragma unroll
    for (int k = 0; k < 16; k++)
        stage[(t & 63) | (k << 6) | (hi2 << 10)] = v[k];   // stride-1 in lane
    __syncthreads();

    // Stage B: thread covers local 0..7 (src 0..5, 12..13), k' = local 8..11
    // (src 14..17); butterflies on k' bits 2..3 = src bits 16..17.
#pragma unroll
    for (int k = 0; k < 16; k++) v[k] = stage[t + (k << 8)];  // stride-1
#pragma unroll
    for (int kb = 2; kb < 4; kb++) {
        int m = 1 << kb;
        u64 t2 = T2[2 + kb], n2 = NT2[2 + kb];   // bits 16,17
#pragma unroll
        for (int k = 0; k < 16; k++)
            if (!(k & m)) bflyT(v[k], v[k + m], t2, n2);
    }

    // permutation: source bits 0..5 = t&63, 6..11 = fix, 12..13 = t>>6,
    // 14..17 = k'. Target = XOR of column masks.
    int off2 = off_lo | ((t >> 6) << 12);        // source bits 0..13
    unsigned tb = 0;
#pragma unroll
    for (int p = 0; p < 14; p++)
        tb ^= P.m[p] & (0u - (unsigned)((off2 >> p) & 1));
    unsigned m14 = P.m[14], m15 = P.m[15], m16 = P.m[16], m17 = P.m[17];
    int bb = b * NSTATE;
    float inv = LAST ? (g_invnorm[b] * C6) : 0.f;   // fold tan-scale into inv
    int hh = (t >> 6) & 3;                       // source bits 12..13

    if (!LAST) {
#pragma unroll
        for (int k = 0; k < 16; k++) {
            unsigned tg = tb;
            if (k & 1) tg ^= m14;
            if (k & 2) tg ^= m15;
            if (k & 4) tg ^= m16;
            if (k & 8) tg ^= m17;
            dst[bb + tg] = cmulp(v[k], Hout[hh | (k << 2)]); // Phi_out,hi
        }
    } else {
#pragma unroll
        for (int k = 0; k < 16; k++) {
            unsigned tg = tb;
            if (k & 1) tg ^= m14;
            if (k & 2) tg ^= m15;
            if (k & 4) tg ^= m16;
            if (k & 8) tg ^= m17;
            float ax, ay; up(v[k], ax, ay);
            outF[bb + tg] = sqrtf(fmaf(ax, ax, ay * ay)) * inv;
        }
    }
}

__global__ void norm_kernel() {
    int b = threadIdx.x;
    if (b < NB) {
        float s = 0.f;
        for (int i = 0; i < NCHK; i++) s += g_partial[b * NCHK + i];
        g_invnorm[b] = 1.0f / sqrtf(s);
    }
}

// ---------------------------------------------------------------------------
// Host side
// ---------------------------------------------------------------------------
static PermM makePerm(int l) {
    PermM P;
    for (int p = 0; p < 18; p++) {
        unsigned idx = 1u << p;
        for (int i = 0; i < 18; i++) {
            int c  = (i + l) % 18;
            int t  = (i + l + 1) % 18;
            int cb = 17 - c;
            int tb = 17 - t;
            idx ^= ((idx >> cb) & 1u) << tb;
        }
        P.m[p] = idx;
    }
    return P;
}

extern "C" void kernel_launch(void* const* d_in, const int* in_sizes, int n_in,
                              void* d_out, int out_size)
{
    const float* x      = (const float*)d_in[0];
    const float* params = (const float*)d_in[1];
    if (n_in >= 2 && in_sizes[0] < in_sizes[1]) {  // defensive input-order guard
        x      = (const float*)d_in[1];
        params = (const float*)d_in[0];
    }

    cudaFuncSetAttribute(pass_low<true>,
                         cudaFuncAttributeMaxDynamicSharedMemorySize, CHUNK * 8);
    cudaFuncSetAttribute(pass_low<false>,
                         cudaFuncAttributeMaxDynamicSharedMemorySize, CHUNK * 8);
    cudaFuncSetAttribute(pass_high<false>,
                         cudaFuncAttributeMaxDynamicSharedMemorySize, CHUNK * 8);
    cudaFuncSetAttribute(pass_high<true>,
                         cudaFuncAttributeMaxDynamicSharedMemorySize, CHUNK * 8);

    PermM P0 = makePerm(0);
    PermM P1 = makePerm(1);

    u64* sa = nullptr; u64* sb = nullptr;
    cudaGetSymbolAddress((void**)&sa, g_sa);
    cudaGetSymbolAddress((void**)&sb, g_sb);

    // Layer 0
    pass_low<true>  <<<NB * NCHK, 256, CHUNK * 8>>>(x, params, sa, nullptr);
    norm_kernel     <<<1, 32>>>();
    pass_high<false><<<NB * NCHK, 256, CHUNK * 8>>>(params, P0, sa, sb, nullptr);
    // Layer 1 (pass3 in-place)
    pass_low<false> <<<NB * NCHK, 256, CHUNK * 8>>>(nullptr, params + 54, sb, sb);
    pass_high<true> <<<NB * NCHK, 256, CHUNK * 8>>>(params + 54, P1, sb, nullptr,
                                                    (float*)d_out);
}

// round 15
// speedup vs baseline: 1.3264x; 1.3264x over previous
#include <cuda_runtime.h>
#include <math.h>

// ---------------------------------------------------------------------------
// QNetBlock: 18-qubit state-vector sim, batch 32.
//   out = | P2 * D2 * P1 * D1 * x | / ||x||
// Per layer D = Phi_out * (tensor RY) * Phi_in (Phi diagonal, RY real).
// RY butterflies in packed f32x2 (classic cos/sin form — R6 proven config).
// Bit split: low = bits 0..11, high = 12..17.  4-pass schedule:
//   pass1: Phi_in,lo(L0) + RY bits 0..11.
//   pass2: [Phi_in,hi(L0)*Phi_out,lo(L0)] + RY 12..17 + Phi_out,hi(L0) + P1.
//   pass3: Phi_in,lo(L1) + RY bits 0..11 (in-place).
//   pass4: Phi_in,hi(L1) + RY 12..17; Phi_out(L1) dropped; P2 + |amp|/||x||
//          (norm reduction folded in; no separate norm kernel).
// R13: persistent 2-chunk CTAs (grid 1024, tables reused), pass_low
// ownerships {0,9,10,11}/{1..4}/{5..8} so bit 0 lives in registers ->
// LDG.128 loads + STS.128 on transpose 1; swizzle preserves bit 0.
// ---------------------------------------------------------------------------

#define NB      32
#define NSTATE  (1 << 18)
#define CHUNK   4096
#define NCHK    64

typedef unsigned long long u64;

__device__ u64   g_sa[(size_t)NB * NSTATE];   // 64 MB
__device__ u64   g_sb[(size_t)NB * NSTATE];   // 64 MB
__device__ float g_partial[NB * NCHK];

struct PermM { unsigned m[18]; };

// ---- packed f32x2 helpers --------------------------------------------------
__device__ __forceinline__ u64 pk(float x, float y) {
    u64 r; asm("mov.b64 %0,{%1,%2};" : "=l"(r) : "f"(x), "f"(y)); return r;
}
__device__ __forceinline__ void up(u64 a, float& x, float& y) {
    asm("mov.b64 {%0,%1},%2;" : "=f"(x), "=f"(y) : "l"(a));
}
__device__ __forceinline__ u64 f2mul(u64 a, u64 b) {
    u64 r; asm("mul.rn.f32x2 %0,%1,%2;" : "=l"(r) : "l"(a), "l"(b)); return r;
}
__device__ __forceinline__ u64 f2fma(u64 a, u64 b, u64 c) {
    u64 r; asm("fma.rn.f32x2 %0,%1,%2,%3;" : "=l"(r) : "l"(a), "l"(b), "l"(c)); return r;
}
__device__ __forceinline__ u64 cmulp(u64 a, u64 b) {
    float ax, ay, bx, by; up(a, ax, ay); up(b, bx, by);
    return pk(fmaf(ax, bx, -ay * by), fmaf(ax, by, ay * bx));
}
// RY butterfly on packed complex: A' = c*A - s*B ; B' = s*A + c*B
__device__ __forceinline__ void bfly2(u64& A, u64& B, u64 c2, u64 s2, u64 ns2) {
    u64 tA = f2mul(ns2, B);
    u64 tB = f2mul(c2,  B);
    u64 nA = f2fma(c2, A, tA);
    B      = f2fma(s2, A, tB);
    A      = nA;
}

// swizzle preserving bit 0 (keeps 16B pairs adjacent & aligned):
// flips addr bits 1..4 by addr bits 5..8.  <=2-way bank-pair conflicts
// (the 64-bit floor) for every ownership pattern below.
__device__ __forceinline__ int swv(int i) { return i ^ (((i >> 5) & 15) << 1); }

// ---------------------------------------------------------------------------
// pass_low: one layer's RY gates on bits 0..11 + Phi_in,lo at load.
// Persistent: grid 1024, CTA does chunks ch and ch+32. 256 thr x 16 amps.
// Ownership A: bits {0,9,10,11} (vectorized global load; bit 0 in k&1)
// Ownership B: bits {1,2,3,4};  C: bits {5,6,7,8} (coalesced store).
// ---------------------------------------------------------------------------
template<bool FIRST>
__global__ void __launch_bounds__(256, 3)
pass_low(const float* __restrict__ x, const float* __restrict__ params,
         u64* __restrict__ dst, const u64* __restrict__ src)
{
    extern __shared__ u64 smem[];          // 4096 u64 = 32 KB
    __shared__ float sp[54];
    __shared__ u64   C2[12], S2[12], NS2[12], Tin[16];
    __shared__ float wsum[8];

    int t = threadIdx.x;
    int b = blockIdx.x >> 5;

    if (t < 54) sp[t] = params[t];
    __syncthreads();

    // ---- tables (once per CTA) ----
    if (t < 12) {                          // RY for bit p = t (wire 17-t)
        float s, c; sincosf(0.5f * sp[(17 - t) * 3 + 1], &s, &c);
        C2[t] = pk(c, c); S2[t] = pk(s, s); NS2[t] = pk(-s, -s);
    } else if (t >= 32 && t < 48) {        // Phi_in over k-bits {0,9,10,11}
        int k = t - 32; float a = 0.f;
        if (k & 1) a += sp[17 * 3 + 0];                 // bit 0  -> wire 17
#pragma unroll
        for (int j = 0; j < 3; j++)                     // bits 9..11 -> wires 8..6
            if ((k >> (1 + j)) & 1) a += sp[(8 - j) * 3 + 0];
        float s, c; sincosf(a, &s, &c); Tin[k] = pk(c, s);
    }
    // per-thread Phi_in base: elem bits 1..8 = t, plus global -sum/2
    float ang = 0.f;
#pragma unroll
    for (int p = 0; p < 12; p++) {
        float ph = sp[(17 - p) * 3 + 0];
        ang -= 0.5f * ph;
        if (p >= 1 && p <= 8 && ((t >> (p - 1)) & 1)) ang += ph;
    }
    float fs, fc; sincosf(ang, &fs, &fc);
    u64 pf0 = pk(fc, fs);
    __syncthreads();                       // tables ready

    for (int cc = 0; cc < 2; cc++) {
        int ch   = (blockIdx.x & 31) | (cc << 5);
        int base = b * NSTATE + ch * CHUNK;

        u64 v[16];
        float xr[16];
        if (FIRST) {
            float ss = 0.f;
#pragma unroll
            for (int j = 0; j < 8; j++) {              // elem = (t<<1)|(j<<9) (+1)
                float2 xv = ((const float2*)x)[(base + (t << 1) + (j << 9)) >> 1];
                xr[2 * j] = xv.x; xr[2 * j + 1] = xv.y;
                ss += xv.x * xv.x + xv.y * xv.y;
            }
#pragma unroll
            for (int o = 16; o; o >>= 1) ss += __shfl_down_sync(0xffffffffu, ss, o);
            if ((t & 31) == 0) wsum[t >> 5] = ss;
        } else {
#pragma unroll
            for (int j = 0; j < 8; j++) {
                ulonglong2 w = ((const ulonglong2*)src)[(base + (t << 1) + (j << 9)) >> 1];
                v[2 * j] = w.x; v[2 * j + 1] = w.y;
            }
        }
        __syncthreads();   // wsum ready; prev-iteration smem reads complete
        if (FIRST && t == 0) {
            float s = 0.f;
            for (int i = 0; i < 8; i++) s += wsum[i];
            g_partial[b * NCHK + ch] = s;  // deterministic fixed-order sum
        }

        // Phi_in,lo  (FIRST: real input -> one packed mul per amp)
#pragma unroll
        for (int k = 0; k < 16; k++) {
            u64 fk = cmulp(pf0, Tin[k]);
            if (FIRST) v[k] = f2mul(pk(xr[k], xr[k]), fk);
            else       v[k] = cmulp(v[k], fk);
        }

        // Ownership A: elem = (k&1) | t<<1 | (k>>1)<<9; RY bits {0,9,10,11}
        {
            u64 c2 = C2[0], s2 = S2[0], n2 = NS2[0];   // bit 0: m = 1
#pragma unroll
            for (int k = 0; k < 16; k += 2) bfly2(v[k], v[k + 1], c2, s2, n2);
        }
#pragma unroll
        for (int kb = 1; kb < 4; kb++) {               // bits 9..11: m = 2,4,8
            int m = 1 << kb;
            u64 c2 = C2[8 + kb], s2 = S2[8 + kb], n2 = NS2[8 + kb];
#pragma unroll
            for (int k = 0; k < 16; k++)
                if (!(k & m)) bfly2(v[k], v[k + m], c2, s2, n2);
        }
#pragma unroll
        for (int j = 0; j < 8; j++) {                  // STS.128 (pairs = bit 0)
            int e = (t << 1) | (j << 9);               // even
            ((ulonglong2*)smem)[swv(e) >> 1] = make_ulonglong2(v[2 * j], v[2 * j + 1]);
        }
        __syncthreads();

        // Ownership B: elem = (t&1) | k<<1 | (t>>1)<<5; RY bits 1..4
#pragma unroll
        for (int k = 0; k < 16; k++)
            v[k] = smem[swv((t & 1) | (k << 1) | ((t >> 1) << 5))];
#pragma unroll
        for (int kb = 0; kb < 4; kb++) {
            int m = 1 << kb;
            u64 c2 = C2[1 + kb], s2 = S2[1 + kb], n2 = NS2[1 + kb];
#pragma unroll
            for (int k = 0; k < 16; k++)
                if (!(k & m)) bfly2(v[k], v[k + m], c2, s2, n2);
        }
#pragma unroll
        for (int k = 0; k < 16; k++)
            smem[swv((t & 1) | (k << 1) | ((t >> 1) << 5))] = v[k];
        __syncthreads();

        // Ownership C: elem = (t&31) | k<<5 | (t>>5)<<9; RY bits 5..8, store
#pragma unroll
        for (int k = 0; k < 16; k++)
            v[k] = smem[swv((t & 31) | (k << 5) | ((t >> 5) << 9))];
#pragma unroll
        for (int kb = 0; kb < 4; kb++) {
            int m = 1 << kb;
            u64 c2 = C2[5 + kb], s2 = S2[5 + kb], n2 = NS2[5 + kb];
#pragma unroll
            for (int k = 0; k < 16; k++)
                if (!(k & m)) bfly2(v[k], v[k + m], c2, s2, n2);
        }
#pragma unroll
        for (int k = 0; k < 16; k++)                   // coalesced (lanes = bits 0..4)
            dst[base + ((t & 31) | (k << 5) | ((t >> 5) << 9))] = v[k];
    }
}

// ---------------------------------------------------------------------------
// pass_high: one layer's RY gates on bits 12..17 in two stages through one
// stride-1 smem transpose, diagonals at load/store, CNOT-ring permutation as
// XOR-mask scatter at store. Persistent: grid 1024, CTA does fix and fix+32.
// LAST: per-CTA deterministic norm reduction (replaces norm kernel) and
// writes |amp| * invnorm to the float output.
// ---------------------------------------------------------------------------
template<bool LAST>
__global__ void __launch_bounds__(256, 3)
pass_high(const float* __restrict__ params, PermM P,
          const u64* __restrict__ src, u64* __restrict__ dst,
          float* __restrict__ outF)
{
    extern __shared__ u64 stage[];               // 4096 u64 = 32 KB
    __shared__ float sp[54];
    __shared__ u64   C2[6], S2[6], NS2[6], Hin[64], Hout[64];
    __shared__ float sInv;

    int t   = threadIdx.x;
    int hi2 = t >> 6;                            // source bits 16..17 (stage A)
    int b   = blockIdx.x >> 5;

    if (t < 54) sp[t] = params[t];
    if (LAST && t == 0) {                        // fold norm: fixed-order sum
        float s = 0.f;
        for (int i = 0; i < NCHK; i++) s += g_partial[b * NCHK + i];
        sInv = 1.0f / sqrtf(s);
    }
    __syncthreads();

    if (t < 6) {                                 // RY for bit 12+t = wire 5-t
        float s, c; sincosf(0.5f * sp[(5 - t) * 3 + 1], &s, &c);
        C2[t] = pk(c, c); S2[t] = pk(s, s); NS2[t] = pk(-s, -s);
    } else if (t >= 64 && t < 128) {             // tables over bits 12..17
        int kk = t - 64;
        float ai = 0.f, ao = 0.f;
#pragma unroll
        for (int j = 0; j < 6; j++) {
            float ph = sp[(5 - j) * 3 + 0];
            float om = sp[(5 - j) * 3 + 2];
            ai -= 0.5f * ph;  ao -= 0.5f * om;
            if ((kk >> j) & 1) { ai += ph; ao += om; }
        }
        float s, c;
        sincosf(ai, &s, &c); Hin[kk] = pk(c, s);
        if (!LAST) { sincosf(ao, &s, &c); Hout[kk] = pk(c, s); }
    }
    __syncthreads();                             // tables ready
    float inv = LAST ? sInv : 0.f;

    for (int cc = 0; cc < 2; cc++) {
        int fix    = (blockIdx.x & 31) | (cc << 5);   // source bits 6..11
        int off_lo = (t & 63) | (fix << 6);           // source bits 0..11
        int base   = b * NSTATE + off_lo + (hi2 << 16);

        u64 v[16];
#pragma unroll
        for (int k = 0; k < 16; k++) v[k] = src[base + (k << 12)];  // coalesced

        u64 pg = pk(1.f, 0.f);                   // Phi_out,lo(L0), !LAST only
        if (!LAST) {
            float ang = 0.f;
#pragma unroll
            for (int p = 0; p < 12; p++) {
                float om = sp[(17 - p) * 3 + 2];
                ang -= 0.5f * om;
                if ((off_lo >> p) & 1) ang += om;
            }
            float s, c; sincosf(ang, &s, &c); pg = pk(c, s);
        }
        __syncthreads();                         // prev-iteration stage reads done

        // load diagonal: source bits 12..17 = k | hi2<<4
#pragma unroll
        for (int k = 0; k < 16; k++) {
            u64 f = Hin[k | (hi2 << 4)];
            if (!LAST) f = cmulp(pg, f);
            v[k] = cmulp(v[k], f);
        }

        // Stage A: RY bits 12..15 (k bits 0..3)
#pragma unroll
        for (int kb = 0; kb < 4; kb++) {
            int m = 1 << kb;
            u64 c2 = C2[kb], s2 = S2[kb], n2 = NS2[kb];
#pragma unroll
            for (int k = 0; k < 16; k++)
                if (!(k & m)) bfly2(v[k], v[k + m], c2, s2, n2);
        }

        // transpose: local L = srcbits{0..5} | {12..15}<<6 | {16..17}<<10
#pragma unroll
        for (int k = 0; k < 16; k++)
            stage[(t & 63) | (k << 6) | (hi2 << 10)] = v[k];   // stride-1
        __syncthreads();

        // Stage B: thread covers local 0..7 (src 0..5, 12..13), k' = local
        // 8..11 (src 14..17); butterflies on k' bits 2..3 = src bits 16..17.
#pragma unroll
        for (int k = 0; k < 16; k++) v[k] = stage[t + (k << 8)];  // stride-1
#pragma unroll
        for (int kb = 2; kb < 4; kb++) {
            int m = 1 << kb;
            u64 c2 = C2[2 + kb], s2 = S2[2 + kb], n2 = NS2[2 + kb]; // bits 16,17
#pragma unroll
            for (int k = 0; k < 16; k++)
                if (!(k & m)) bfly2(v[k], v[k + m], c2, s2, n2);
        }

        // permutation: source bits 0..5 = t&63, 6..11 = fix, 12..13 = t>>6,
        // 14..17 = k'. Target = XOR of column masks.
        int off2 = off_lo | ((t >> 6) << 12);    // source bits 0..13
        unsigned tb = 0;
#pragma unroll
        for (int p = 0; p < 14; p++)
            tb ^= P.m[p] & (0u - (unsigned)((off2 >> p) & 1));
        unsigned m14 = P.m[14], m15 = P.m[15], m16 = P.m[16], m17 = P.m[17];
        int bb = b * NSTATE;
        int hh = (t >> 6) & 3;                   // source bits 12..13

        if (!LAST) {
#pragma unroll
            for (int k = 0; k < 16; k++) {
                unsigned tg = tb;
                if (k & 1) tg ^= m14;
                if (k & 2) tg ^= m15;
                if (k & 4) tg ^= m16;
                if (k & 8) tg ^= m17;
                dst[bb + tg] = cmulp(v[k], Hout[hh | (k << 2)]); // Phi_out,hi
            }
        } else {
#pragma unroll
            for (int k = 0; k < 16; k++) {
                unsigned tg = tb;
                if (k & 1) tg ^= m14;
                if (k & 2) tg ^= m15;
                if (k & 4) tg ^= m16;
                if (k & 8) tg ^= m17;
                float ax, ay; up(v[k], ax, ay);
                outF[bb + tg] = sqrtf(fmaf(ax, ax, ay * ay)) * inv;
            }
        }
    }
}

// ---------------------------------------------------------------------------
// Host side
// ---------------------------------------------------------------------------
static PermM makePerm(int l) {
    PermM P;
    for (int p = 0; p < 18; p++) {
        unsigned idx = 1u << p;
        for (int i = 0; i < 18; i++) {
            int c  = (i + l) % 18;
            int t  = (i + l + 1) % 18;
            int cb = 17 - c;
            int tb = 17 - t;
            idx ^= ((idx >> cb) & 1u) << tb;
        }
        P.m[p] = idx;
    }
    return P;
}

extern "C" void kernel_launch(void* const* d_in, const int* in_sizes, int n_in,
                              void* d_out, int out_size)
{
    const float* x      = (const float*)d_in[0];
    const float* params = (const float*)d_in[1];
    if (n_in >= 2 && in_sizes[0] < in_sizes[1]) {  // defensive input-order guard
        x      = (const float*)d_in[1];
        params = (const float*)d_in[0];
    }

    cudaFuncSetAttribute(pass_low<true>,
                         cudaFuncAttributeMaxDynamicSharedMemorySize, CHUNK * 8);
    cudaFuncSetAttribute(pass_low<false>,
                         cudaFuncAttributeMaxDynamicSharedMemorySize, CHUNK * 8);
    cudaFuncSetAttribute(pass_high<false>,
                         cudaFuncAttributeMaxDynamicSharedMemorySize, CHUNK * 8);
    cudaFuncSetAttribute(pass_high<true>,
                         cudaFuncAttributeMaxDynamicSharedMemorySize, CHUNK * 8);

    PermM P0 = makePerm(0);
    PermM P1 = makePerm(1);

    u64* sa = nullptr; u64* sb = nullptr;
    cudaGetSymbolAddress((void**)&sa, g_sa);
    cudaGetSymbolAddress((void**)&sb, g_sb);

    const int GRID = NB * 32;   // 1024 persistent 2-chunk CTAs

    // Layer 0
    pass_low<true>  <<<GRID, 256, CHUNK * 8>>>(x, params, sa, nullptr);
    pass_high<false><<<GRID, 256, CHUNK * 8>>>(params, P0, sa, sb, nullptr);
    // Layer 1 (pass3 in-place)
    pass_low<false> <<<GRID, 256, CHUNK * 8>>>(nullptr, params + 54, sb, sb);
    pass_high<true> <<<GRID, 256, CHUNK * 8>>>(params + 54, P1, sb, nullptr,
                                               (float*)d_out);
}